// round 7
// baseline (speedup 1.0000x reference)
#include <cuda_runtime.h>
#include <stdint.h>

// MyDropout: out = x * mask; mask = JAX partitionable-threefry dropout
// (seed 42, p=0.1), columns < 64 zeroed. x: [16384, 4096] f32, N = 67108864.
//
//   bits(i) = o0 ^ o1, (o0,o1) = threefry2x32(key=(0,42), ctr=(0,i))
//   keep  <=>  bits < 0xE6666600   (== (bits>>9) < 0x733333 == uniform < 0.9f)
//
// Rotates are done as IMAD.WIDE (fma pipe): w = x * 2^r gives {lo=x<<r,
// hi=x>>(32-r)}; the following (lo|hi)^x0 is ONE 3-input LOP3 (alu pipe).
// This rebalances the round from 2-alu/0.5-fma to 1-alu/2-fma.

__device__ __forceinline__ uint32_t tf_rotx(uint32_t v, int r, uint32_t x0) {
    uint64_t w = (uint64_t)v * ((uint64_t)1u << r);   // IMAD.WIDE.U32 (fma pipe)
    uint32_t lo = (uint32_t)w;
    uint32_t hi = (uint32_t)(w >> 32);
    return (lo | hi) ^ x0;                            // single LOP3 (alu pipe)
}

#define TFW_ROUND(r) do { x0 += x1; x1 = tf_rotx(x1, (r), x0); } while (0)

__device__ __forceinline__ uint32_t tf_bits(uint32_t i) {
    const uint32_t k0 = 0u;
    const uint32_t k1 = 42u;
    const uint32_t k2 = 0x1BD11BDAu ^ k0 ^ k1;  // 0x1BD11BF0

    uint32_t x1 = i + k1;       // ctr_lo + k1
    uint32_t x0 = x1;           // round 1: x0 = (ctr_hi + k0) + x1 = 0 + x1
    x1 = tf_rotx(x1, 13, x0);   // rest of round 1
    TFW_ROUND(15); TFW_ROUND(26); TFW_ROUND(6);
    x0 += k1; x1 += k2 + 1u;
    TFW_ROUND(17); TFW_ROUND(29); TFW_ROUND(16); TFW_ROUND(24);
    x0 += k2; x1 += k0 + 2u;
    TFW_ROUND(13); TFW_ROUND(15); TFW_ROUND(26); TFW_ROUND(6);
    x0 += k0; x1 += k1 + 3u;
    TFW_ROUND(17); TFW_ROUND(29); TFW_ROUND(16); TFW_ROUND(24);
    x0 += k1; x1 += k2 + 4u;
    TFW_ROUND(13); TFW_ROUND(15); TFW_ROUND(26); TFW_ROUND(6);
    x0 += k2; x1 += k0 + 5u;
    return x0 ^ x1;             // partitionable 32-bit output
}

__global__ __launch_bounds__(256) void mydropout_kernel(
    const float4* __restrict__ x, float4* __restrict__ out) {
    const uint32_t KEEP_LT = 0xE6666600u;     // bits < this  <=>  keep
    const float scale = (float)(1.0 / 0.9);

    uint32_t tid = blockIdx.x * blockDim.x + threadIdx.x;  // one float4 / thread
    uint32_t g = tid << 2;                                 // element index
    uint32_t col = g & 4095u;                              // column (row width 4096)

    if (col < 64u) {
        // K=64 leading columns zeroed; float4-aligned, whole vector is zero.
        out[tid] = make_float4(0.f, 0.f, 0.f, 0.f);
        return;
    }

    float4 a = x[tid];

    uint32_t b0 = tf_bits(g + 0u);
    uint32_t b1 = tf_bits(g + 1u);
    uint32_t b2 = tf_bits(g + 2u);
    uint32_t b3 = tf_bits(g + 3u);

    float4 r;
    r.x = a.x * ((b0 < KEEP_LT) ? scale : 0.f);
    r.y = a.y * ((b1 < KEEP_LT) ? scale : 0.f);
    r.z = a.z * ((b2 < KEEP_LT) ? scale : 0.f);
    r.w = a.w * ((b3 < KEEP_LT) ? scale : 0.f);

    out[tid] = r;
}

extern "C" void kernel_launch(void* const* d_in, const int* in_sizes, int n_in,
                              void* d_out, int out_size) {
    const float4* x = (const float4*)d_in[0];
    float4* out = (float4*)d_out;
    const int threads = 256;
    const int blocks = 16777216 / threads;  // N/4 threads
    mydropout_kernel<<<blocks, threads>>>(x, out);
}